// round 5
// baseline (speedup 1.0000x reference)
#include <cuda_runtime.h>
#include <stdint.h>
#include <math.h>

#define BATCH 32
#define SEQ   8400
#define NLAB  80
#define DIM   256
#define NQ    300
#define CAND  512
#define RPB   48              // rows per block -> 175 blocks per batch
#define BPB   (SEQ / RPB)     // 175 blocks per batch

// Scratch (allocation-free per harness rules)
__device__ unsigned int g_scores_u[BATCH * SEQ];  // sortable-uint scores
__device__ int          g_topk[BATCH * NQ];
__device__ unsigned int g_arrive[BATCH];          // zero-init; self-resetting

__device__ __forceinline__ unsigned int f32_sortable(float v) {
    unsigned int u = __float_as_uint(v);
    return (u & 0x80000000u) ? ~u : (u | 0x80000000u);  // ascending-order uint
}

// ---------------------------------------------------------------------------
// Fused kernel: phase A computes 48 row-maxes per block (fully coalesced);
// the LAST block of each batch (per-batch atomic counter) then runs the exact
// top-300 select for that batch, overlapping with other batches' phase A.
// ---------------------------------------------------------------------------
__global__ void __launch_bounds__(256) scores_topk_kernel(const float* __restrict__ cls) {
    __shared__ float              part[RPB * 20];      // 960 floats
    __shared__ unsigned int       s_w1[8], s_w2[8];
    __shared__ unsigned int       s_r12, s_r3;
    __shared__ unsigned int       s_woff[8];
    __shared__ unsigned int       s_cnt;
    __shared__ unsigned int       s_last;
    __shared__ unsigned long long s_cand[CAND];

    const int t     = threadIdx.x;
    const int lane  = t & 31;
    const int wid   = t >> 5;
    const int batch = blockIdx.x / BPB;
    const unsigned FULL = 0xFFFFFFFFu;

    // ================= Phase A: 48 row maxes =================
    {
        const float4* base = (const float4*)cls + (size_t)blockIdx.x * (RPB * 20);
        #pragma unroll
        for (int i = 0; i < 4; ++i) {
            int idx = t + 256 * i;
            if (idx < RPB * 20) {
                float4 v = __ldg(&base[idx]);
                part[idx] = fmaxf(fmaxf(v.x, v.y), fmaxf(v.z, v.w));
            }
        }
        __syncthreads();
        if (t < RPB * 4) {                // 192 threads: 4 per row
            int row = t >> 2;
            int p   = t & 3;
            const float* q = &part[row * 20 + p * 5];
            float m = q[0];
            #pragma unroll
            for (int j = 1; j < 5; ++j) m = fmaxf(m, q[j]);
            m = fmaxf(m, __shfl_xor_sync(FULL, m, 1));
            m = fmaxf(m, __shfl_xor_sync(FULL, m, 2));
            if (p == 0)
                g_scores_u[blockIdx.x * RPB + row] = f32_sortable(m);
        }
    }
    __threadfence();
    __syncthreads();
    if (t == 0)
        s_last = (atomicAdd(&g_arrive[batch], 1u) == BPB - 1);
    __syncthreads();
    if (!s_last) return;

    // ================= Phase B: top-300 for this batch (last block only) ====
    const unsigned int* sc = g_scores_u + batch * SEQ;

    // 8 uint4 + tail -> 33 values per thread, indices derivable from (k,j)
    uint4 q[8];
    #pragma unroll
    for (int k = 0; k < 8; ++k)
        q[k] = __ldg(&((const uint4*)sc)[t + 256 * k]);
    const bool hasTail = (t < SEQ - 8192);     // 208
    unsigned int vt = hasTail ? __ldg(&sc[8192 + t]) : 0u;

    // ---- block max ----
    unsigned int mx = vt;
    #pragma unroll
    for (int k = 0; k < 8; ++k) {
        mx = max(mx, max(max(q[k].x, q[k].y), max(q[k].z, q[k].w)));
    }
    #pragma unroll
    for (int o = 16; o > 0; o >>= 1) mx = max(mx, __shfl_xor_sync(FULL, mx, o));
    if (lane == 0) s_w1[wid] = mx;
    __syncthreads();
    if (t < 8) {
        unsigned int m2 = s_w1[t];
        m2 = max(m2, __shfl_xor_sync(0xFFu, m2, 4));
        m2 = max(m2, __shfl_xor_sync(0xFFu, m2, 2));
        m2 = max(m2, __shfl_xor_sync(0xFFu, m2, 1));
        if (t == 0) s_r12 = m2;
    }
    __syncthreads();
    const unsigned int M = s_r12;

    // ---- quaternary search: largest 22-bit T with count(v >= T<<10) >= NQ ----
    unsigned int lo = 0, hi = (M >> 10) + 1;
    while (hi - lo > 1) {
        unsigned int d  = hi - lo;
        unsigned int m1 = lo + (d >> 2); if (m1 == lo) m1 = lo + 1;
        unsigned int m2 = lo + (d >> 1); if (m2 == lo) m2 = lo + 1;
        unsigned int m3 = lo + d - (d >> 2); if (m3 >= hi) m3 = hi - 1;
        const unsigned int t1 = m1 << 10, t2 = m2 << 10, t3 = m3 << 10;

        unsigned int c12 = 0, c3 = 0;
        #pragma unroll
        for (int k = 0; k < 8; ++k) {
            c12 += (q[k].x >= t1) + (q[k].y >= t1) + (q[k].z >= t1) + (q[k].w >= t1);
            c12 += ((q[k].x >= t2) + (q[k].y >= t2) + (q[k].z >= t2) + (q[k].w >= t2)) << 16;
            c3  += (q[k].x >= t3) + (q[k].y >= t3) + (q[k].z >= t3) + (q[k].w >= t3);
        }
        if (hasTail) { c12 += (vt >= t1) + ((vt >= t2) << 16); c3 += (vt >= t3); }

        #pragma unroll
        for (int o = 16; o > 0; o >>= 1) {
            c12 += __shfl_xor_sync(FULL, c12, o);
            c3  += __shfl_xor_sync(FULL, c3,  o);
        }
        if (lane == 0) { s_w1[wid] = c12; s_w2[wid] = c3; }
        __syncthreads();
        if (t < 8) {
            unsigned int a = s_w1[t], bb = s_w2[t];
            a  += __shfl_xor_sync(0xFFu, a, 4);  bb += __shfl_xor_sync(0xFFu, bb, 4);
            a  += __shfl_xor_sync(0xFFu, a, 2);  bb += __shfl_xor_sync(0xFFu, bb, 2);
            a  += __shfl_xor_sync(0xFFu, a, 1);  bb += __shfl_xor_sync(0xFFu, bb, 1);
            if (t == 0) { s_r12 = a; s_r3 = bb; }
        }
        __syncthreads();
        const unsigned int cnt1 = s_r12 & 0xFFFFu;
        const unsigned int cnt2 = s_r12 >> 16;
        const unsigned int cnt3 = s_r3;

        if      (cnt3 >= NQ) lo = m3;
        else if (cnt2 >= NQ) { lo = m2; hi = m3; }
        else if (cnt1 >= NQ) { lo = m1; hi = m2; }
        else                 hi = m1;
    }
    const unsigned int T = lo << 10;

    // ---- compact candidates via block prefix scan ----
    int myc = 0;
    #pragma unroll
    for (int k = 0; k < 8; ++k)
        myc += (q[k].x >= T) + (q[k].y >= T) + (q[k].z >= T) + (q[k].w >= T);
    myc += (hasTail && vt >= T);

    int inc = myc;
    #pragma unroll
    for (int o = 1; o < 32; o <<= 1) {
        int t2 = __shfl_up_sync(FULL, inc, o);
        if (lane >= o) inc += t2;
    }
    if (lane == 31) s_w1[wid] = (unsigned)inc;
    __syncthreads();
    if (t < 8) {
        unsigned int v = s_w1[t];
        unsigned int i2 = v;
        #pragma unroll
        for (int o = 1; o < 8; o <<= 1) {
            unsigned int t2 = __shfl_up_sync(0xFFu, i2, o);
            if (t >= o) i2 += t2;
        }
        s_woff[t] = i2 - v;
        if (t == 7) s_cnt = i2;
    }
    __syncthreads();

    int pos = (int)s_woff[wid] + (inc - myc);
    #pragma unroll
    for (int k = 0; k < 8; ++k) {
        const unsigned int vals[4] = { q[k].x, q[k].y, q[k].z, q[k].w };
        #pragma unroll
        for (int j = 0; j < 4; ++j) {
            if (vals[j] >= T) {
                int idx = 4 * (t + 256 * k) + j;
                if (pos < CAND)
                    s_cand[pos] = ((unsigned long long)vals[j] << 32) |
                                  (unsigned int)(SEQ - 1 - idx);
                ++pos;
            }
        }
    }
    if (hasTail && vt >= T) {
        if (pos < CAND)
            s_cand[pos] = ((unsigned long long)vt << 32) |
                          (unsigned int)(SEQ - 1 - (8192 + t));
    }
    __syncthreads();

    // ---- sync-free ranking: rank = #{j: key_j > key_i} ----
    const int cntC = (int)min(s_cnt, (unsigned)CAND);
    for (int c = t; c < cntC; c += 256) {
        const unsigned long long mine = s_cand[c];
        int rank = 0;
        for (int j = 0; j < cntC; ++j)
            rank += (s_cand[j] > mine);
        if (rank < NQ)
            g_topk[batch * NQ + rank] =
                SEQ - 1 - (int)(unsigned int)(mine & 0xFFFFFFFFull);
    }

    // reset counter for deterministic graph replay
    if (t == 0) g_arrive[batch] = 0u;
}

// ---------------------------------------------------------------------------
// Gather kernel: one 96-thread block per (b, q), all float4.
// Output layout (flattened tuple, return order):
//   [0]            init_reference_points (B,NQ,4)
//   [+B*NQ*4]      target                (B,NQ,256)
//   [+B*NQ*256]    enc_topk_logits       (B,NQ,80)
//   [+B*NQ*80]     enc_topk_bboxes       (B,NQ,4)
// ---------------------------------------------------------------------------
__global__ void __launch_bounds__(96) gather_kernel(const float* __restrict__ cls,
                              const float* __restrict__ coord,
                              const float* __restrict__ mem,
                              float* __restrict__ out) {
    const int bq = blockIdx.x;
    const int b  = bq / NQ;
    const int t  = threadIdx.x;
    const int s  = __ldg(&g_topk[bq]);
    const size_t src = (size_t)b * SEQ + (size_t)s;

    float* out_tgt  = out + (size_t)BATCH * NQ * 4;
    float* out_log  = out_tgt + (size_t)BATCH * NQ * DIM;
    float* out_bbox = out_log + (size_t)BATCH * NQ * NLAB;

    if (t < 64) {                                    // target: 256 floats
        const float4* m4 = (const float4*)(mem + src * DIM);
        float4*       o4 = (float4*)(out_tgt + (size_t)bq * DIM);
        o4[t] = __ldg(&m4[t]);
    } else if (t < 84) {                             // logits: 80 floats
        const int j = t - 64;
        const float4* c4 = (const float4*)(cls + src * NLAB);
        float4*       o4 = (float4*)(out_log + (size_t)bq * NLAB);
        o4[j] = __ldg(&c4[j]);
    } else if (t == 84) {                            // coords: 4 floats
        float4 v = __ldg((const float4*)(coord + src * 4));
        *(float4*)(out + (size_t)bq * 4) = v;
        float4 sg;
        sg.x = 1.0f / (1.0f + __expf(-v.x));
        sg.y = 1.0f / (1.0f + __expf(-v.y));
        sg.z = 1.0f / (1.0f + __expf(-v.z));
        sg.w = 1.0f / (1.0f + __expf(-v.w));
        *(float4*)(out_bbox + (size_t)bq * 4) = sg;
    }
}

// ---------------------------------------------------------------------------
extern "C" void kernel_launch(void* const* d_in, const int* in_sizes, int n_in,
                              void* d_out, int out_size) {
    const float* cls   = (const float*)d_in[0];  // (32, 8400, 80)
    const float* coord = (const float*)d_in[1];  // (32, 8400, 4)
    const float* mem   = (const float*)d_in[2];  // (32, 8400, 256)
    float* out = (float*)d_out;

    scores_topk_kernel<<<BATCH * BPB, 256>>>(cls);   // 5600 blocks
    gather_kernel<<<BATCH * NQ, 96>>>(cls, coord, mem, out);
}

// round 6
// speedup vs baseline: 2.4267x; 2.4267x over previous
#include <cuda_runtime.h>
#include <stdint.h>
#include <math.h>

#define BATCH 32
#define SEQ   8400
#define NLAB  80
#define DIM   256
#define NQ    300
#define CAND  512
#define RPB   48      // rows per block in scores kernel
#define QPW   4       // queries per warp in gather kernel

// Scratch (allocation-free per harness rules)
__device__ unsigned int g_scores_u[BATCH * SEQ];  // sortable-uint scores
__device__ int          g_topk[BATCH * NQ];

__device__ __forceinline__ unsigned int f32_sortable(float v) {
    unsigned int u = __float_as_uint(v);
    return (u & 0x80000000u) ? ~u : (u | 0x80000000u);  // ascending-order uint
}

// ---------------------------------------------------------------------------
// Kernel 1: scores[b][s] = max over 80 labels (sortable uint out).
// Best measured config (R3): RPB=48, 256 threads, smem transpose.
// ---------------------------------------------------------------------------
__global__ void __launch_bounds__(256) scores_kernel(const float* __restrict__ cls) {
    __shared__ float part[RPB * 20];  // 960 floats

    const int t = threadIdx.x;
    const float4* base = (const float4*)cls + (size_t)blockIdx.x * (RPB * 20);

    #pragma unroll
    for (int i = 0; i < 4; ++i) {
        int idx = t + 256 * i;
        if (idx < RPB * 20) {
            float4 v = __ldg(&base[idx]);
            part[idx] = fmaxf(fmaxf(v.x, v.y), fmaxf(v.z, v.w));
        }
    }
    __syncthreads();

    if (t < RPB * 4) {                 // 192 threads: 4 per row
        int row = t >> 2;
        int p   = t & 3;
        const float* q = &part[row * 20 + p * 5];
        float m = q[0];
        #pragma unroll
        for (int j = 1; j < 5; ++j) m = fmaxf(m, q[j]);
        m = fmaxf(m, __shfl_xor_sync(0xFFFFFFFFu, m, 1));
        m = fmaxf(m, __shfl_xor_sync(0xFFFFFFFFu, m, 2));
        if (p == 0)
            g_scores_u[blockIdx.x * RPB + row] = f32_sortable(m);
    }
}

// ---------------------------------------------------------------------------
// Kernel 2: per-batch exact top-300, sorted desc, jax tie-break.
// Registers hold the values; quaternary search finds the 22-bit threshold;
// block-scan compaction; sync-free all-vs-all ranking.
// ---------------------------------------------------------------------------
__global__ void __launch_bounds__(1024) topk_kernel() {
    __shared__ unsigned int       s_wA[32];
    __shared__ unsigned int       s_wB[32];
    __shared__ unsigned int       s_r12, s_r3;
    __shared__ unsigned int       s_woff[32];
    __shared__ unsigned int       s_cnt;
    __shared__ unsigned long long s_cand[CAND];

    const int b    = blockIdx.x;
    const int tid  = threadIdx.x;
    const int lane = tid & 31;
    const int wid  = tid >> 5;
    const unsigned FULL = 0xFFFFFFFFu;

    const unsigned int* sc = g_scores_u + b * SEQ;

    uint4 va = ((const uint4*)sc)[tid];
    uint4 vb = ((const uint4*)sc)[tid + 1024];
    const bool hasTail = (tid < SEQ - 8192);           // 208
    unsigned int vt = hasTail ? sc[8192 + tid] : 0u;

    unsigned int vv[9];
    int si[9];
    vv[0]=va.x; vv[1]=va.y; vv[2]=va.z; vv[3]=va.w;
    vv[4]=vb.x; vv[5]=vb.y; vv[6]=vb.z; vv[7]=vb.w;
    vv[8]=hasTail ? vt : 0u;
    #pragma unroll
    for (int k = 0; k < 4; ++k) { si[k] = 4*tid + k; si[4+k] = 4096 + 4*tid + k; }
    si[8] = 8192 + tid;

    // ---- block max ----
    unsigned int mx = 0;
    #pragma unroll
    for (int k = 0; k < 9; ++k) mx = max(mx, vv[k]);
    #pragma unroll
    for (int o = 16; o > 0; o >>= 1) mx = max(mx, __shfl_xor_sync(FULL, mx, o));
    if (lane == 0) s_wA[wid] = mx;
    __syncthreads();
    if (tid < 32) {
        unsigned int m2 = s_wA[tid];
        #pragma unroll
        for (int o = 16; o > 0; o >>= 1) m2 = max(m2, __shfl_xor_sync(FULL, m2, o));
        if (tid == 0) s_r12 = m2;
    }
    __syncthreads();
    const unsigned int M = s_r12;

    // ---- quaternary search ----
    unsigned int lo = 0, hi = (M >> 10) + 1;
    while (hi - lo > 1) {
        unsigned int d  = hi - lo;
        unsigned int m1 = lo + (d >> 2); if (m1 == lo) m1 = lo + 1;
        unsigned int m2 = lo + (d >> 1); if (m2 == lo) m2 = lo + 1;
        unsigned int m3 = lo + d - (d >> 2); if (m3 >= hi) m3 = hi - 1;
        const unsigned int t1 = m1 << 10, t2 = m2 << 10, t3 = m3 << 10;

        unsigned int c12 = 0, c3 = 0;
        #pragma unroll
        for (int k = 0; k < 8; ++k) {
            unsigned int v = vv[k];
            c12 += (v >= t1) + ((v >= t2) << 16);
            c3  += (v >= t3);
        }
        if (hasTail) {
            unsigned int v = vv[8];
            c12 += (v >= t1) + ((v >= t2) << 16);
            c3  += (v >= t3);
        }
        #pragma unroll
        for (int o = 16; o > 0; o >>= 1) {
            c12 += __shfl_xor_sync(FULL, c12, o);
            c3  += __shfl_xor_sync(FULL, c3,  o);
        }
        if (lane == 0) { s_wA[wid] = c12; s_wB[wid] = c3; }
        __syncthreads();
        if (tid < 32) {
            unsigned int a = s_wA[tid], bb = s_wB[tid];
            #pragma unroll
            for (int o = 16; o > 0; o >>= 1) {
                a  += __shfl_xor_sync(FULL, a,  o);
                bb += __shfl_xor_sync(FULL, bb, o);
            }
            if (tid == 0) { s_r12 = a; s_r3 = bb; }
        }
        __syncthreads();
        const unsigned int cnt1 = s_r12 & 0xFFFFu;
        const unsigned int cnt2 = s_r12 >> 16;
        const unsigned int cnt3 = s_r3;

        if      (cnt3 >= NQ) lo = m3;
        else if (cnt2 >= NQ) { lo = m2; hi = m3; }
        else if (cnt1 >= NQ) { lo = m1; hi = m2; }
        else                 hi = m1;
    }
    const unsigned int T = lo << 10;

    // ---- compact candidates via block prefix scan ----
    bool hit[9];
    int myc = 0;
    #pragma unroll
    for (int k = 0; k < 8; ++k) { hit[k] = (vv[k] >= T); myc += hit[k]; }
    hit[8] = hasTail && (vv[8] >= T); myc += hit[8];

    int inc = myc;
    #pragma unroll
    for (int o = 1; o < 32; o <<= 1) {
        int t2 = __shfl_up_sync(FULL, inc, o);
        if (lane >= o) inc += t2;
    }
    if (lane == 31) s_wA[wid] = (unsigned)inc;
    __syncthreads();
    if (tid < 32) {
        unsigned int v = s_wA[tid];
        unsigned int i2 = v;
        #pragma unroll
        for (int o = 1; o < 32; o <<= 1) {
            unsigned int t2 = __shfl_up_sync(FULL, i2, o);
            if (tid >= o) i2 += t2;
        }
        s_woff[tid] = i2 - v;
        if (tid == 31) s_cnt = i2;
    }
    __syncthreads();

    int pos = (int)s_woff[wid] + (inc - myc);
    #pragma unroll
    for (int k = 0; k < 9; ++k) {
        if (hit[k]) {
            if (pos < CAND)
                s_cand[pos] = ((unsigned long long)vv[k] << 32) |
                              (unsigned int)(SEQ - 1 - si[k]);
            ++pos;
        }
    }
    __syncthreads();

    // ---- sync-free ranking ----
    const int cntC = (int)min(s_cnt, (unsigned)CAND);
    if (tid < cntC) {
        const unsigned long long mine = s_cand[tid];
        int rank = 0;
        for (int j = 0; j < cntC; ++j)
            rank += (s_cand[j] > mine);
        if (rank < NQ)
            g_topk[b * NQ + rank] =
                SEQ - 1 - (int)(unsigned int)(mine & 0xFFFFFFFFull);
    }
}

// ---------------------------------------------------------------------------
// Kernel 3: gather, latency-optimized. 300 blocks x 256 threads; each warp
// owns QPW=4 consecutive queries. All index loads, then all gather loads
// batched (>= 10 independent LDGs in flight), then stores.
// Per query: mem row 64 float4 -> lanes j, j+32; logits 20 float4 -> lanes
// 0..19; coord float4 + sigmoid -> lane 24+i.
// Output layout (flattened tuple, return order):
//   [0]            init_reference_points (B,NQ,4)
//   [+B*NQ*4]      target                (B,NQ,256)
//   [+B*NQ*256]    enc_topk_logits       (B,NQ,80)
//   [+B*NQ*80]     enc_topk_bboxes       (B,NQ,4)
// ---------------------------------------------------------------------------
__global__ void __launch_bounds__(256) gather_kernel(const float* __restrict__ cls,
                              const float* __restrict__ coord,
                              const float* __restrict__ mem,
                              float* __restrict__ out) {
    const int lane = threadIdx.x & 31;
    const int wid  = threadIdx.x >> 5;
    const int bq0  = (blockIdx.x * 8 + wid) * QPW;

    float* out_tgt  = out + (size_t)BATCH * NQ * 4;
    float* out_log  = out_tgt + (size_t)BATCH * NQ * DIM;
    float* out_bbox = out_log + (size_t)BATCH * NQ * NLAB;

    // phase 1: all index loads (independent, broadcast)
    size_t src[QPW];
    #pragma unroll
    for (int i = 0; i < QPW; ++i) {
        const int bq = bq0 + i;
        const int s  = __ldg(&g_topk[bq]);
        src[i] = (size_t)(bq / NQ) * SEQ + (size_t)s;
    }

    // phase 2: all gather loads
    float4 m0[QPW], m1[QPW], lg[QPW], cd[QPW];
    #pragma unroll
    for (int i = 0; i < QPW; ++i) {
        const float4* m4 = (const float4*)(mem + src[i] * DIM);
        m0[i] = __ldg(&m4[lane]);
        m1[i] = __ldg(&m4[lane + 32]);
        if (lane < 20)
            lg[i] = __ldg(&((const float4*)(cls + src[i] * NLAB))[lane]);
        if (lane == 24 + i)
            cd[i] = __ldg((const float4*)(coord + src[i] * 4));
    }

    // phase 3: stores
    #pragma unroll
    for (int i = 0; i < QPW; ++i) {
        const int bq = bq0 + i;
        float4* o4 = (float4*)(out_tgt + (size_t)bq * DIM);
        o4[lane]      = m0[i];
        o4[lane + 32] = m1[i];
        if (lane < 20)
            ((float4*)(out_log + (size_t)bq * NLAB))[lane] = lg[i];
        if (lane == 24 + i) {
            float4 v = cd[i];
            *(float4*)(out + (size_t)bq * 4) = v;
            float4 sg;
            sg.x = 1.0f / (1.0f + __expf(-v.x));
            sg.y = 1.0f / (1.0f + __expf(-v.y));
            sg.z = 1.0f / (1.0f + __expf(-v.z));
            sg.w = 1.0f / (1.0f + __expf(-v.w));
            *(float4*)(out_bbox + (size_t)bq * 4) = sg;
        }
    }
}

// ---------------------------------------------------------------------------
extern "C" void kernel_launch(void* const* d_in, const int* in_sizes, int n_in,
                              void* d_out, int out_size) {
    const float* cls   = (const float*)d_in[0];  // (32, 8400, 80)
    const float* coord = (const float*)d_in[1];  // (32, 8400, 4)
    const float* mem   = (const float*)d_in[2];  // (32, 8400, 256)
    float* out = (float*)d_out;

    scores_kernel<<<(BATCH * SEQ) / RPB, 256>>>(cls);   // 5600 blocks
    topk_kernel<<<BATCH, 1024>>>();
    gather_kernel<<<(BATCH * NQ) / (8 * QPW), 256>>>(cls, coord, mem, out);  // 300 blocks
}